// round 14
// baseline (speedup 1.0000x reference)
#include <cuda_runtime.h>
#include <cuda_bf16.h>
#include <cstdint>

// R13 (terminal) = R11 champion (30.72us) + __launch_bounds__(256, 8).
// R11 load order preserved exactly (z staging first, dir after); R12 showed
// hoisting dir gained nothing. Occupancy bound caps regs at 32 (R11 had 38,
// occ 63.6%) at zero cost.
//
// Certified floor model (R1..R12 evidence):
//   176 MB compulsory z traffic (44B rows touch every 32B sector)
//   / ~6.28 TB/s path-independent bandwidth cap (LDG == LDG.128 == TMA)
//   + ~2.7us warm-replay residual  ==  ~30.7us.
// Closed levers: z pinning (R6 regress, R8 null), v8 hinted LDG (R4 regress),
// TMA (null), persistent grid (R10 regress), block 512 (null), block BAR
// removal (~null), occupancy (non-binding).
//
// L2 steady-state plan:
//   z1/z2 : __ldcs streaming (protects dir/out residency across replays)
//   dir   : evict_last hint load, out: evict_last hint store.
// z_3 remains unread (reference discards c_3).

constexpr int TPB  = 256;
constexpr int ROWS = 256;
constexpr int WORDS_PER_BLOCK = ROWS * 11;       // 2816 floats
constexpr int F4_PER_WARP     = 32 * 11 / 4;     // 88 float4 per warp slice
constexpr int WORDS_PER_WARP  = 32 * 11;         // 352

__device__ __forceinline__ uint64_t policy_last() {
    uint64_t p;
    asm("createpolicy.fractional.L2::evict_last.b64 %0, 1.0;" : "=l"(p));
    return p;
}
__device__ __forceinline__ float4 ldg_f4_last(const float4* p, uint64_t pol) {
    float4 v;
    asm("ld.global.nc.L2::cache_hint.v4.f32 {%0,%1,%2,%3}, [%4], %5;"
        : "=f"(v.x), "=f"(v.y), "=f"(v.z), "=f"(v.w) : "l"(p), "l"(pol));
    return v;
}
__device__ __forceinline__ void stg_f32_last(float* p, float v, uint64_t pol) {
    asm volatile("st.global.L2::cache_hint.f32 [%0], %1, %2;"
                 :: "l"(p), "f"(v), "l"(pol) : "memory");
}

__global__ __launch_bounds__(TPB, 8)
void yolo_zone_kernel(const float4* __restrict__ z1v,
                      const float4* __restrict__ z2v,
                      const float4* __restrict__ dir,
                      float* __restrict__ out,
                      int n, long nf4)
{
    __shared__ float s1[WORDS_PER_BLOCK];
    __shared__ float s2[WORDS_PER_BLOCK];

    const int t    = threadIdx.x;
    const int wid  = t >> 5;
    const int lane = t & 31;

    // Warp-private slice: rows [blk*256 + wid*32, +32) -> 88 float4, base
    // wid*1408 B (16B-aligned).
    const long warp_base4 = (long)blockIdx.x * (WORDS_PER_BLOCK / 4)
                          + (long)wid * F4_PER_WARP;
    float4* s1w = reinterpret_cast<float4*>(s1 + wid * WORDS_PER_WARP);
    float4* s2w = reinterpret_cast<float4*>(s2 + wid * WORDS_PER_WARP);

    // Stage 88 float4 per array with 32 lanes: k=0,1 full, k=2 partial (24).
    #pragma unroll
    for (int k = 0; k < 3; k++) {
        int  sidx = lane + k * 32;
        long g    = warp_base4 + sidx;
        if (sidx < F4_PER_WARP && g < nf4) {
            s1w[sidx] = __ldcs(z1v + g);
            s2w[sidx] = __ldcs(z2v + g);
        }
    }

    // dir: coalesced float4/row; overlaps staging latency.
    const int row = blockIdx.x * ROWS + t;
    const uint64_t pol_last = policy_last();
    float4 d = make_float4(0.f, 0.f, 0.f, 0.f);
    if (row < n) d = ldg_f4_last(dir + row, pol_last);

    __syncwarp();          // only this warp's own loads must be visible
    if (row >= n) return;

    const int w = wid * WORDS_PER_WARP + lane * 11;  // conflict-free (11 ⊥ 32)
    float a0 = s1[w + 0], a1 = s1[w + 1], a2 = s1[w + 2], a3 = s1[w + 3];
    float b0 = s2[w + 0], b1 = s2[w + 1], b2 = s2[w + 2], b3 = s2[w + 3];

    // Centers and direction vector (division by 2 exact in fp32).
    float dx = (b0 + b2) * 0.5f - (a0 + a2) * 0.5f;
    float dy = -((b1 + b3) * 0.5f - (a1 + a3) * 0.5f);

    // degrees(atan2), truncate toward zero (matches .astype(int32)).
    float phi = atan2f(dy, dx) * 57.29577951308232f;
    int phi_long = (int)phi;

    // python-style mod 360 of (90 - phi_long); range [-90, 270] -> one fixup.
    int m = 90 - phi_long;
    if (m < 0) m += 360;
    if (m >= 360) m -= 360;

    // zone = floor((m + 45) / 90) mod 4
    int zone = ((m + 45) / 90) & 3;

    float r = (zone == 0) ? d.x : (zone == 1) ? d.y : (zone == 2) ? d.z : d.w;
    stg_f32_last(out + row, r, pol_last);
}

extern "C" void kernel_launch(void* const* d_in, const int* in_sizes, int n_in,
                              void* d_out, int out_size)
{
    const float4* z1v = (const float4*)d_in[0];
    const float4* z2v = (const float4*)d_in[1];
    // d_in[2] (z_3) intentionally unused — reference discards c_3.
    const float4* dir = (const float4*)d_in[3];
    float*        out = (float*)d_out;

    int  n   = out_size;
    long nf4 = ((long)n * 11) / 4;   // exact: 2e6*11 divisible by 4

    int grid = (n + ROWS - 1) / ROWS;
    yolo_zone_kernel<<<grid, TPB>>>(z1v, z2v, dir, out, n, nf4);
}

// round 15
// speedup vs baseline: 1.0052x; 1.0052x over previous
#include <cuda_runtime.h>
#include <cuda_bf16.h>
#include <cstdint>

// R14 (terminal) = R11 verbatim — the best-measured configuration (30.72us).
// R13 showed the launch_bounds reg-cap nets <=0 (ptxas rematerialization);
// natural allocation (38 regs, occ ~64%) is empirically fastest. Occupancy
// proven non-binding.
//
// Certified floor model:
//   176 MB compulsory z traffic (44B-stride rows with 16B useful touch ALL
//   32B sectors: rows 2/5/7 of each 8-row period straddle two sectors)
//   / ~6.28 TB/s path-independent bandwidth cap (LDG == LDG.128 == TMA)
//   + ~2.7us warm-replay residual (graph fixed cost, non-kernel-addressable)
//   == ~30.7us.
// Closed levers: z pinning (R6 regress, R8 null), v8 hinted LDG (R4 regress),
// TMA (null), persistent grid (R10 regress), block 512 (null), occupancy
// (non-binding, R12/R13), load order (null, R12).
//
// L2 steady-state plan:
//   z1/z2 : __ldcs streaming (protects dir/out L2 residency across replays)
//   dir   : evict_last hint load, out: evict_last hint store.
// z_3 remains unread (reference discards c_3).

constexpr int TPB  = 256;
constexpr int ROWS = 256;
constexpr int WORDS_PER_BLOCK = ROWS * 11;       // 2816 floats
constexpr int F4_PER_WARP     = 32 * 11 / 4;     // 88 float4 per warp slice
constexpr int WORDS_PER_WARP  = 32 * 11;         // 352

__device__ __forceinline__ uint64_t policy_last() {
    uint64_t p;
    asm("createpolicy.fractional.L2::evict_last.b64 %0, 1.0;" : "=l"(p));
    return p;
}
__device__ __forceinline__ float4 ldg_f4_last(const float4* p, uint64_t pol) {
    float4 v;
    asm("ld.global.nc.L2::cache_hint.v4.f32 {%0,%1,%2,%3}, [%4], %5;"
        : "=f"(v.x), "=f"(v.y), "=f"(v.z), "=f"(v.w) : "l"(p), "l"(pol));
    return v;
}
__device__ __forceinline__ void stg_f32_last(float* p, float v, uint64_t pol) {
    asm volatile("st.global.L2::cache_hint.f32 [%0], %1, %2;"
                 :: "l"(p), "f"(v), "l"(pol) : "memory");
}

__global__ __launch_bounds__(TPB)
void yolo_zone_kernel(const float4* __restrict__ z1v,
                      const float4* __restrict__ z2v,
                      const float4* __restrict__ dir,
                      float* __restrict__ out,
                      int n, long nf4)
{
    __shared__ float s1[WORDS_PER_BLOCK];
    __shared__ float s2[WORDS_PER_BLOCK];

    const int t    = threadIdx.x;
    const int wid  = t >> 5;
    const int lane = t & 31;

    // Warp-private slice: rows [blk*256 + wid*32, +32) -> 88 float4, base
    // wid*1408 B (16B-aligned).
    const long warp_base4 = (long)blockIdx.x * (WORDS_PER_BLOCK / 4)
                          + (long)wid * F4_PER_WARP;
    float4* s1w = reinterpret_cast<float4*>(s1 + wid * WORDS_PER_WARP);
    float4* s2w = reinterpret_cast<float4*>(s2 + wid * WORDS_PER_WARP);

    // Stage 88 float4 per array with 32 lanes: k=0,1 full, k=2 partial (24).
    #pragma unroll
    for (int k = 0; k < 3; k++) {
        int  sidx = lane + k * 32;
        long g    = warp_base4 + sidx;
        if (sidx < F4_PER_WARP && g < nf4) {
            s1w[sidx] = __ldcs(z1v + g);
            s2w[sidx] = __ldcs(z2v + g);
        }
    }

    // dir: coalesced float4/row; overlaps staging latency.
    const int row = blockIdx.x * ROWS + t;
    const uint64_t pol_last = policy_last();
    float4 d = make_float4(0.f, 0.f, 0.f, 0.f);
    if (row < n) d = ldg_f4_last(dir + row, pol_last);

    __syncwarp();          // only this warp's own loads must be visible
    if (row >= n) return;

    const int w = wid * WORDS_PER_WARP + lane * 11;  // conflict-free (11 ⊥ 32)
    float a0 = s1[w + 0], a1 = s1[w + 1], a2 = s1[w + 2], a3 = s1[w + 3];
    float b0 = s2[w + 0], b1 = s2[w + 1], b2 = s2[w + 2], b3 = s2[w + 3];

    // Centers and direction vector (division by 2 exact in fp32).
    float dx = (b0 + b2) * 0.5f - (a0 + a2) * 0.5f;
    float dy = -((b1 + b3) * 0.5f - (a1 + a3) * 0.5f);

    // degrees(atan2), truncate toward zero (matches .astype(int32)).
    float phi = atan2f(dy, dx) * 57.29577951308232f;
    int phi_long = (int)phi;

    // python-style mod 360 of (90 - phi_long); range [-90, 270] -> one fixup.
    int m = 90 - phi_long;
    if (m < 0) m += 360;
    if (m >= 360) m -= 360;

    // zone = floor((m + 45) / 90) mod 4
    int zone = ((m + 45) / 90) & 3;

    float r = (zone == 0) ? d.x : (zone == 1) ? d.y : (zone == 2) ? d.z : d.w;
    stg_f32_last(out + row, r, pol_last);
}

extern "C" void kernel_launch(void* const* d_in, const int* in_sizes, int n_in,
                              void* d_out, int out_size)
{
    const float4* z1v = (const float4*)d_in[0];
    const float4* z2v = (const float4*)d_in[1];
    // d_in[2] (z_3) intentionally unused — reference discards c_3.
    const float4* dir = (const float4*)d_in[3];
    float*        out = (float*)d_out;

    int  n   = out_size;
    long nf4 = ((long)n * 11) / 4;   // exact: 2e6*11 divisible by 4

    int grid = (n + ROWS - 1) / ROWS;
    yolo_zone_kernel<<<grid, TPB>>>(z1v, z2v, dir, out, n, nf4);
}

// round 16
// speedup vs baseline: 1.0365x; 1.0311x over previous
#include <cuda_runtime.h>
#include <cuda_bf16.h>
#include <cstdint>

// R15 (terminal) = R11/R14 champion, byte-identical (30.72us, measured twice).
//
// Certified floor model:
//   176 MB compulsory z traffic (44B-stride rows with 16B useful touch ALL
//   32B sectors: rows 2/5/7 of each 8-row period straddle two sectors)
//   / ~6.28 TB/s path-independent bandwidth cap (LDG == LDG.128 == TMA)
//   + ~2.7us warm-replay residual (graph fixed cost, non-kernel-addressable)
//   == ~30.7us.
// z cross-replay L2 retention impossible in principle: identical replay order
// means the region read last is always read last -> evicted before reuse.
// Closed levers: z pinning (R6 regress, R8 null), v8 hinted LDG (R4 regress),
// TMA (null), persistent grid (R10 regress), block 512 (null), occupancy
// (non-binding, R12/R13), load order (null, R12), atan2f replacement
// (compute non-binding; truncation-boundary correctness risk).
//
// L2 steady-state plan:
//   z1/z2 : __ldcs streaming (protects dir/out L2 residency across replays)
//   dir   : evict_last hint load, out: evict_last hint store.
// z_3 remains unread (reference discards c_3).

constexpr int TPB  = 256;
constexpr int ROWS = 256;
constexpr int WORDS_PER_BLOCK = ROWS * 11;       // 2816 floats
constexpr int F4_PER_WARP     = 32 * 11 / 4;     // 88 float4 per warp slice
constexpr int WORDS_PER_WARP  = 32 * 11;         // 352

__device__ __forceinline__ uint64_t policy_last() {
    uint64_t p;
    asm("createpolicy.fractional.L2::evict_last.b64 %0, 1.0;" : "=l"(p));
    return p;
}
__device__ __forceinline__ float4 ldg_f4_last(const float4* p, uint64_t pol) {
    float4 v;
    asm("ld.global.nc.L2::cache_hint.v4.f32 {%0,%1,%2,%3}, [%4], %5;"
        : "=f"(v.x), "=f"(v.y), "=f"(v.z), "=f"(v.w) : "l"(p), "l"(pol));
    return v;
}
__device__ __forceinline__ void stg_f32_last(float* p, float v, uint64_t pol) {
    asm volatile("st.global.L2::cache_hint.f32 [%0], %1, %2;"
                 :: "l"(p), "f"(v), "l"(pol) : "memory");
}

__global__ __launch_bounds__(TPB)
void yolo_zone_kernel(const float4* __restrict__ z1v,
                      const float4* __restrict__ z2v,
                      const float4* __restrict__ dir,
                      float* __restrict__ out,
                      int n, long nf4)
{
    __shared__ float s1[WORDS_PER_BLOCK];
    __shared__ float s2[WORDS_PER_BLOCK];

    const int t    = threadIdx.x;
    const int wid  = t >> 5;
    const int lane = t & 31;

    // Warp-private slice: rows [blk*256 + wid*32, +32) -> 88 float4, base
    // wid*1408 B (16B-aligned).
    const long warp_base4 = (long)blockIdx.x * (WORDS_PER_BLOCK / 4)
                          + (long)wid * F4_PER_WARP;
    float4* s1w = reinterpret_cast<float4*>(s1 + wid * WORDS_PER_WARP);
    float4* s2w = reinterpret_cast<float4*>(s2 + wid * WORDS_PER_WARP);

    // Stage 88 float4 per array with 32 lanes: k=0,1 full, k=2 partial (24).
    #pragma unroll
    for (int k = 0; k < 3; k++) {
        int  sidx = lane + k * 32;
        long g    = warp_base4 + sidx;
        if (sidx < F4_PER_WARP && g < nf4) {
            s1w[sidx] = __ldcs(z1v + g);
            s2w[sidx] = __ldcs(z2v + g);
        }
    }

    // dir: coalesced float4/row; overlaps staging latency.
    const int row = blockIdx.x * ROWS + t;
    const uint64_t pol_last = policy_last();
    float4 d = make_float4(0.f, 0.f, 0.f, 0.f);
    if (row < n) d = ldg_f4_last(dir + row, pol_last);

    __syncwarp();          // only this warp's own loads must be visible
    if (row >= n) return;

    const int w = wid * WORDS_PER_WARP + lane * 11;  // conflict-free (11 ⊥ 32)
    float a0 = s1[w + 0], a1 = s1[w + 1], a2 = s1[w + 2], a3 = s1[w + 3];
    float b0 = s2[w + 0], b1 = s2[w + 1], b2 = s2[w + 2], b3 = s2[w + 3];

    // Centers and direction vector (division by 2 exact in fp32).
    float dx = (b0 + b2) * 0.5f - (a0 + a2) * 0.5f;
    float dy = -((b1 + b3) * 0.5f - (a1 + a3) * 0.5f);

    // degrees(atan2), truncate toward zero (matches .astype(int32)).
    float phi = atan2f(dy, dx) * 57.29577951308232f;
    int phi_long = (int)phi;

    // python-style mod 360 of (90 - phi_long); range [-90, 270] -> one fixup.
    int m = 90 - phi_long;
    if (m < 0) m += 360;
    if (m >= 360) m -= 360;

    // zone = floor((m + 45) / 90) mod 4
    int zone = ((m + 45) / 90) & 3;

    float r = (zone == 0) ? d.x : (zone == 1) ? d.y : (zone == 2) ? d.z : d.w;
    stg_f32_last(out + row, r, pol_last);
}

extern "C" void kernel_launch(void* const* d_in, const int* in_sizes, int n_in,
                              void* d_out, int out_size)
{
    const float4* z1v = (const float4*)d_in[0];
    const float4* z2v = (const float4*)d_in[1];
    // d_in[2] (z_3) intentionally unused — reference discards c_3.
    const float4* dir = (const float4*)d_in[3];
    float*        out = (float*)d_out;

    int  n   = out_size;
    long nf4 = ((long)n * 11) / 4;   // exact: 2e6*11 divisible by 4

    int grid = (n + ROWS - 1) / ROWS;
    yolo_zone_kernel<<<grid, TPB>>>(z1v, z2v, dir, out, n, nf4);
}

// round 17
// speedup vs baseline: 1.0399x; 1.0032x over previous
#include <cuda_runtime.h>
#include <cuda_bf16.h>
#include <cstdint>

// R16 (terminal, confirmation run) = R11/R14/R15 champion, byte-identical.
// Three measurements of this exact source: 30.72, 30.72, 29.79 us ->
// inter-session noise ~±0.5us dominates; all R7..R15 variants statistically
// tied on the certified floor.
//
// Certified floor model:
//   176 MB compulsory z traffic (44B-stride rows with 16B useful touch ALL
//   32B sectors: rows 2/5/7 of each 8-row period straddle two sectors)
//   / ~6.2-6.3 TB/s path-independent bandwidth cap (LDG == LDG.128 == TMA)
//   + ~2us warm-replay residual  ==  ~30us measured band.
// z cross-replay L2 retention impossible in principle: identical replay order
// means the region read last is always read last -> evicted before reuse.
// Closed levers: z pinning (R6 regress, R8 null), v8 hinted LDG (R4 regress),
// TMA (null), persistent grid (R10 regress), block 512 (null), occupancy
// (non-binding), load order (null), reg-cap (null), atan2f replacement
// (compute non-binding; truncation-boundary correctness risk).
//
// L2 steady-state plan:
//   z1/z2 : __ldcs streaming (protects dir/out L2 residency across replays)
//   dir   : evict_last hint load, out: evict_last hint store.
// z_3 remains unread (reference discards c_3).

constexpr int TPB  = 256;
constexpr int ROWS = 256;
constexpr int WORDS_PER_BLOCK = ROWS * 11;       // 2816 floats
constexpr int F4_PER_WARP     = 32 * 11 / 4;     // 88 float4 per warp slice
constexpr int WORDS_PER_WARP  = 32 * 11;         // 352

__device__ __forceinline__ uint64_t policy_last() {
    uint64_t p;
    asm("createpolicy.fractional.L2::evict_last.b64 %0, 1.0;" : "=l"(p));
    return p;
}
__device__ __forceinline__ float4 ldg_f4_last(const float4* p, uint64_t pol) {
    float4 v;
    asm("ld.global.nc.L2::cache_hint.v4.f32 {%0,%1,%2,%3}, [%4], %5;"
        : "=f"(v.x), "=f"(v.y), "=f"(v.z), "=f"(v.w) : "l"(p), "l"(pol));
    return v;
}
__device__ __forceinline__ void stg_f32_last(float* p, float v, uint64_t pol) {
    asm volatile("st.global.L2::cache_hint.f32 [%0], %1, %2;"
                 :: "l"(p), "f"(v), "l"(pol) : "memory");
}

__global__ __launch_bounds__(TPB)
void yolo_zone_kernel(const float4* __restrict__ z1v,
                      const float4* __restrict__ z2v,
                      const float4* __restrict__ dir,
                      float* __restrict__ out,
                      int n, long nf4)
{
    __shared__ float s1[WORDS_PER_BLOCK];
    __shared__ float s2[WORDS_PER_BLOCK];

    const int t    = threadIdx.x;
    const int wid  = t >> 5;
    const int lane = t & 31;

    // Warp-private slice: rows [blk*256 + wid*32, +32) -> 88 float4, base
    // wid*1408 B (16B-aligned).
    const long warp_base4 = (long)blockIdx.x * (WORDS_PER_BLOCK / 4)
                          + (long)wid * F4_PER_WARP;
    float4* s1w = reinterpret_cast<float4*>(s1 + wid * WORDS_PER_WARP);
    float4* s2w = reinterpret_cast<float4*>(s2 + wid * WORDS_PER_WARP);

    // Stage 88 float4 per array with 32 lanes: k=0,1 full, k=2 partial (24).
    #pragma unroll
    for (int k = 0; k < 3; k++) {
        int  sidx = lane + k * 32;
        long g    = warp_base4 + sidx;
        if (sidx < F4_PER_WARP && g < nf4) {
            s1w[sidx] = __ldcs(z1v + g);
            s2w[sidx] = __ldcs(z2v + g);
        }
    }

    // dir: coalesced float4/row; overlaps staging latency.
    const int row = blockIdx.x * ROWS + t;
    const uint64_t pol_last = policy_last();
    float4 d = make_float4(0.f, 0.f, 0.f, 0.f);
    if (row < n) d = ldg_f4_last(dir + row, pol_last);

    __syncwarp();          // only this warp's own loads must be visible
    if (row >= n) return;

    const int w = wid * WORDS_PER_WARP + lane * 11;  // conflict-free (11 ⊥ 32)
    float a0 = s1[w + 0], a1 = s1[w + 1], a2 = s1[w + 2], a3 = s1[w + 3];
    float b0 = s2[w + 0], b1 = s2[w + 1], b2 = s2[w + 2], b3 = s2[w + 3];

    // Centers and direction vector (division by 2 exact in fp32).
    float dx = (b0 + b2) * 0.5f - (a0 + a2) * 0.5f;
    float dy = -((b1 + b3) * 0.5f - (a1 + a3) * 0.5f);

    // degrees(atan2), truncate toward zero (matches .astype(int32)).
    float phi = atan2f(dy, dx) * 57.29577951308232f;
    int phi_long = (int)phi;

    // python-style mod 360 of (90 - phi_long); range [-90, 270] -> one fixup.
    int m = 90 - phi_long;
    if (m < 0) m += 360;
    if (m >= 360) m -= 360;

    // zone = floor((m + 45) / 90) mod 4
    int zone = ((m + 45) / 90) & 3;

    float r = (zone == 0) ? d.x : (zone == 1) ? d.y : (zone == 2) ? d.z : d.w;
    stg_f32_last(out + row, r, pol_last);
}

extern "C" void kernel_launch(void* const* d_in, const int* in_sizes, int n_in,
                              void* d_out, int out_size)
{
    const float4* z1v = (const float4*)d_in[0];
    const float4* z2v = (const float4*)d_in[1];
    // d_in[2] (z_3) intentionally unused — reference discards c_3.
    const float4* dir = (const float4*)d_in[3];
    float*        out = (float*)d_out;

    int  n   = out_size;
    long nf4 = ((long)n * 11) / 4;   // exact: 2e6*11 divisible by 4

    int grid = (n + ROWS - 1) / ROWS;
    yolo_zone_kernel<<<grid, TPB>>>(z1v, z2v, dir, out, n, nf4);
}